// round 10
// baseline (speedup 1.0000x reference)
#include <cuda_runtime.h>
#include <stdint.h>

// Problem constants (fixed by the reference: B=4, S=4096, D=2, 3 RK2 steps)
#define BB    4
#define SS    4096
#define WPR   (SS / 32)            // 128 bitmask words per row
#define NWRDS (BB * SS * WPR)      // 2,097,152 words (8 MB)
#define NROWS (BB * SS)            // 16384 rows
#define CAP   96                   // padded index capacity per row (mean 41, sd 6.4)
#define PAD   8                    // zero pad slots per batch
#define PS    (SS + PAD)           // padded per-batch stride (float2 elems)
#define SENT  SS                   // sentinel index -> zero pad slot
#define DT_F      0.1f
#define HALF_DT_F 0.05f
#define EPS_F     1e-8f

// Force tiling: 8 threads per row, 12 indices per thread.
#define T_PER_ROW 8
#define IPT       (CAP / T_PER_ROW)   // 12
#define WPT       (WPR / T_PER_ROW)   // 16 bitmask words per thread (fallback)
#define FBLOCKS   (NROWS * T_PER_ROW / 256)   // 512 blocks in the fused kernel

// ---- scratch (static device globals; no runtime allocation) ----
__device__ __align__(16) uint32_t       g_bits[NWRDS];        // 8 MB bitmask
__device__ __align__(16) unsigned short g_idx[NROWS * CAP];   // 3 MB padded CSR indices
__device__               int            g_cnt[NROWS];         // true nnz per row
__device__ __align__(16) float2         g_ps[BB * PS];        // padded state
__device__ __align__(16) float2         g_sp[BB * PS];        // padded psi_star
__device__ __align__(16) float2         g_k1[NROWS];
__device__               float          g_r[NROWS];
__device__               unsigned       g_bar_count;          // grid barrier
__device__               unsigned       g_bar_gen;

// ============================================================================
// 1) Compress dense fp32 0/1 mask -> bitmask via warp ballots (HBM-bound;
//    the mandatory 256 MB mask read is the floor of the whole problem).
// ============================================================================
__global__ void compress_kernel(const float* __restrict__ mask) {
    const int lane   = threadIdx.x & 31;
    const int warp   = (blockIdx.x * blockDim.x + threadIdx.x) >> 5;
    const int nwarps = (gridDim.x * blockDim.x) >> 5;

    for (size_t w = (size_t)warp * 8; w < (size_t)NWRDS; w += (size_t)nwarps * 8) {
        float v0 = mask[(w + 0) * 32 + lane];
        float v1 = mask[(w + 1) * 32 + lane];
        float v2 = mask[(w + 2) * 32 + lane];
        float v3 = mask[(w + 3) * 32 + lane];
        float v4 = mask[(w + 4) * 32 + lane];
        float v5 = mask[(w + 5) * 32 + lane];
        float v6 = mask[(w + 6) * 32 + lane];
        float v7 = mask[(w + 7) * 32 + lane];

        unsigned b0 = __ballot_sync(0xFFFFFFFFu, v0 != 0.0f);
        unsigned b1 = __ballot_sync(0xFFFFFFFFu, v1 != 0.0f);
        unsigned b2 = __ballot_sync(0xFFFFFFFFu, v2 != 0.0f);
        unsigned b3 = __ballot_sync(0xFFFFFFFFu, v3 != 0.0f);
        unsigned b4 = __ballot_sync(0xFFFFFFFFu, v4 != 0.0f);
        unsigned b5 = __ballot_sync(0xFFFFFFFFu, v5 != 0.0f);
        unsigned b6 = __ballot_sync(0xFFFFFFFFu, v6 != 0.0f);
        unsigned b7 = __ballot_sync(0xFFFFFFFFu, v7 != 0.0f);

        if (lane == 0) {
            uint4* dst = reinterpret_cast<uint4*>(g_bits + w);
            dst[0] = make_uint4(b0, b1, b2, b3);
            dst[1] = make_uint4(b4, b5, b6, b7);
        }
    }
}

// ============================================================================
// 2) Build sentinel-padded CSR lists (one warp per row, deterministic bit
//    order) + copy psi into the padded state array + zero the pad slots.
// ============================================================================
__global__ void build_idx_kernel(const float2* __restrict__ psi) {
    const int gid = blockIdx.x * blockDim.x + threadIdx.x;

    // psi -> padded state; zero pad slots of both padded arrays.
    if (gid < NROWS) {
        const int b = gid >> 12, pos = gid & (SS - 1);
        g_ps[b * PS + pos] = psi[gid];
    } else if (gid < NROWS + BB * PAD) {
        const int k = gid - NROWS;
        const int b = k / PAD, pp = k % PAD;
        g_ps[b * PS + SS + pp] = make_float2(0.0f, 0.0f);
        g_sp[b * PS + SS + pp] = make_float2(0.0f, 0.0f);
    }

    const int lane = threadIdx.x & 31;
    const int row  = gid >> 5;                 // grid sized so row < NROWS
    if (row >= NROWS) return;

    const uint4 w4 = reinterpret_cast<const uint4*>(g_bits + (size_t)row * WPR)[lane];
    const int n = __popc(w4.x) + __popc(w4.y) + __popc(w4.z) + __popc(w4.w);

    int pfx = n;
#pragma unroll
    for (int off = 1; off < 32; off <<= 1) {
        int v = __shfl_up_sync(0xFFFFFFFFu, pfx, off);
        if (lane >= off) pfx += v;
    }
    const int total = __shfl_sync(0xFFFFFFFFu, pfx, 31);
    pfx -= n;  // exclusive

    if (lane == 31) g_cnt[row] = total;

    unsigned short* dst = g_idx + (size_t)row * CAP;

    // Fill the whole row with the sentinel first, then scatter real indices.
#pragma unroll
    for (int i = lane; i < CAP; i += 32) dst[i] = (unsigned short)SENT;
    __syncwarp();

    int slot = pfx;
    const int colbase = lane * 128;
    uint32_t ws[4] = {w4.x, w4.y, w4.z, w4.w};
#pragma unroll
    for (int k = 0; k < 4; k++) {
        uint32_t w = ws[k];
        while (w) {
            int c = __ffs(w) - 1;
            w &= (w - 1);
            if (slot < CAP) dst[slot] = (unsigned short)(colbase + k * 32 + c);
            slot++;
        }
    }
}

// ============================================================================
// Grid-wide software barrier. Valid because all FBLOCKS blocks are resident.
// ============================================================================
__device__ __forceinline__ void grid_barrier() {
    __syncthreads();
    if (threadIdx.x == 0) {
        const unsigned gen = *(volatile unsigned*)&g_bar_gen;  // read BEFORE arrive
        __threadfence();
        const unsigned arrived = atomicAdd(&g_bar_count, 1u) + 1u;
        if (arrived == (unsigned)FBLOCKS) {
            g_bar_count = 0;
            __threadfence();
            atomicAdd(&g_bar_gen, 1u);  // release
        } else {
            while (*(volatile unsigned*)&g_bar_gen == gen) __nanosleep(20);
        }
        __threadfence();
    }
    __syncthreads();
}

// ============================================================================
// Force: unconditional sentinel-padded gather straight from L2-resident state.
// ============================================================================
__device__ __forceinline__ void row_force(const float2* __restrict__ base,
                                          int row, int t,
                                          float& ax, float& ay) {
    ax = 0.0f; ay = 0.0f;
    const int cnt = g_cnt[row];

    if (cnt <= CAP) {
        const uint2* p = reinterpret_cast<const uint2*>(
            g_idx + (size_t)row * CAP + t * IPT);   // t*12 u16 = 24B -> 8B aligned
        uint2 a0 = p[0], a1 = p[1], a2 = p[2];
        int id[IPT];
        id[0]  = (int)(a0.x & 0xFFFFu);  id[1]  = (int)(a0.x >> 16);
        id[2]  = (int)(a0.y & 0xFFFFu);  id[3]  = (int)(a0.y >> 16);
        id[4]  = (int)(a1.x & 0xFFFFu);  id[5]  = (int)(a1.x >> 16);
        id[6]  = (int)(a1.y & 0xFFFFu);  id[7]  = (int)(a1.y >> 16);
        id[8]  = (int)(a2.x & 0xFFFFu);  id[9]  = (int)(a2.x >> 16);
        id[10] = (int)(a2.y & 0xFFFFu);  id[11] = (int)(a2.y >> 16);

#pragma unroll
        for (int j = 0; j < IPT; j++) {    // 12 independent LDG.64, no predication
            float2 v = base[id[j]];
            ax += v.x;
            ay += v.y;
        }
    } else {
        // Correctness fallback (cnt > CAP; probability ~0 but kept for rigor).
        const uint32_t* wr = g_bits + (size_t)row * WPR + t * WPT;
#pragma unroll
        for (int q = 0; q < WPT; q++) {
            uint32_t w = wr[q];
            int wbase = (t * WPT + q) * 32;
            while (w) {
                int c = __ffs(w) - 1;
                w &= (w - 1);
                float2 v = base[wbase + c];
                ax += v.x;
                ay += v.y;
            }
        }
    }

#pragma unroll
    for (int offp = T_PER_ROW / 2; offp > 0; offp >>= 1) {
        ax += __shfl_down_sync(0xFFFFFFFFu, ax, offp, T_PER_ROW);
        ay += __shfl_down_sync(0xFFFFFFFFu, ay, offp, T_PER_ROW);
    }
}

// ============================================================================
// 3) Fused integrator: all 3 RK2 steps (6 force evals) in one launch,
//    separated by grid barriers. Final result written straight to d_out.
// ============================================================================
__global__ void __launch_bounds__(256)
fused_steps_kernel(float2* __restrict__ out) {
    const int gid = blockIdx.x * 256 + threadIdx.x;
    const int row = gid >> 3;          // T_PER_ROW = 8
    const int t   = gid & 7;
    const int b   = row >> 12;
    const int pos = row & (SS - 1);

    float2* __restrict__ pbase = g_ps + b * PS;
    float2* __restrict__ sbase = g_sp + b * PS;

#pragma unroll 1
    for (int step = 0; step < 3; step++) {
        // ---- eval A: k1 = force(p); psi_star = renorm(p + dt*k1) ----
        float ax, ay;
        row_force(pbase, row, t, ax, ay);
        if (t == 0) {
            float2 pi = pbase[pos];
            float  r  = sqrtf(pi.x * pi.x + pi.y * pi.y);
            float k1x = ax - pi.x;
            float k1y = ay - pi.y;
            float sx  = fmaf(DT_F, k1x, pi.x);
            float sy  = fmaf(DT_F, k1y, pi.y);
            float sn  = sqrtf(sx * sx + sy * sy);
            float sc  = r / (sn + EPS_F);
            sbase[pos] = make_float2(sx * sc, sy * sc);
            g_k1[row]  = make_float2(k1x, k1y);
            g_r[row]   = r;
        }
        grid_barrier();

        // ---- eval B: k2 = force(psi_star); p = renorm(p + dt/2*(k1+k2)) ----
        row_force(sbase, row, t, ax, ay);
        if (t == 0) {
            float2 si = sbase[pos];
            float k2x = ax - si.x;
            float k2y = ay - si.y;
            float2 k1 = g_k1[row];
            float2 p  = pbase[pos];
            float  r  = g_r[row];
            float nx  = fmaf(HALF_DT_F, k1.x + k2x, p.x);
            float ny  = fmaf(HALF_DT_F, k1.y + k2y, p.y);
            float nn  = sqrtf(nx * nx + ny * ny);
            float sc  = r / (nn + EPS_F);
            float2 res = make_float2(nx * sc, ny * sc);
            if (step == 2) out[row]   = res;
            else           pbase[pos] = res;
        }
        if (step < 2) grid_barrier();
    }
}

// ============================================================================
// Launch: compress + build + fused integrator. All graph-capturable.
// ============================================================================
extern "C" void kernel_launch(void* const* d_in, const int* in_sizes, int n_in,
                              void* d_out, int out_size) {
    const float* psi  = (const float*)d_in[0];
    const float* mask = (const float*)d_in[1];
    if (n_in >= 2 && in_sizes[0] > in_sizes[1]) {  // defensive: pick by size
        psi  = (const float*)d_in[1];
        mask = (const float*)d_in[0];
    }

    compress_kernel<<<1184, 256>>>(mask);
    build_idx_kernel<<<NROWS * 32 / 256, 256>>>((const float2*)psi);  // 1 warp/row
    fused_steps_kernel<<<FBLOCKS, 256>>>((float2*)d_out);             // 512 blocks, all resident

    (void)out_size;
}

// round 12
// speedup vs baseline: 1.2182x; 1.2182x over previous
#include <cuda_runtime.h>
#include <stdint.h>

// Problem constants (fixed by the reference: B=4, S=4096, D=2, 3 RK2 steps)
#define BB    4
#define SS    4096
#define WPR   (SS / 32)            // 128 bitmask words per row
#define NWRDS (BB * SS * WPR)      // 8 MB bitmask
#define NROWS (BB * SS)            // 16384 rows
#define CAP   80                   // padded index capacity (mean 41, sd 6.4; 6 sigma)
#define PS    (SS + 8)             // padded per-batch stride (float2 elems)
#define SENT  SS                   // sentinel index -> zero pad slot (in smem)
#define DT_F      0.1f
#define HALF_DT_F 0.05f
#define EPS_F     1e-8f

// Eval tiling: 8 threads per row, 32 rows per block (256 threads).
#define T_PER_ROW 8
#define IPT       (CAP / T_PER_ROW)   // 10 indices per thread
#define WPT       (WPR / T_PER_ROW)   // 16 bitmask words per thread (fallback)
#define ROWS_PB   32
#define EGRID     (NROWS / ROWS_PB)   // 512 blocks

// Bitmask bit convention (OURS, not lane-major!):
//   word W = 4*i + k  (i = 0..31, k = 0..3), bit b  <->  column 128*i + 4*b + k
// Chosen so the compress stream can use raw __ballot_sync on float4 lanes.

// ---- scratch (static device globals; no runtime allocation) ----
__device__ __align__(16) uint32_t       g_bits[NWRDS];
__device__ __align__(16) unsigned short g_idx[NROWS * CAP];   // sentinel-padded CSR
__device__               int            g_cnt[NROWS];         // true nnz per row
__device__ __align__(16) float2         g_ps[BB * PS];        // state p (padded stride)
__device__ __align__(16) float2         g_sp[BB * PS];        // psi_star
__device__ __align__(16) float2         g_k1[NROWS];
__device__               float          g_r[NROWS];

// ============================================================================
// 1) MERGED: compress mask -> bitmask, build CSR indices, AND compute step-1
//    evalA (k1, psi_star, r) — all in one DRAM-bound pass over the 256 MB mask.
//    One warp per row. The ALU/gather work hides under the HBM stream.
// ============================================================================
__global__ void __launch_bounds__(256)
fused_compress_evalA1(const float* __restrict__ mask,
                      const float2* __restrict__ psi) {
    const int lane = threadIdx.x & 31;
    const int row  = (blockIdx.x * blockDim.x + threadIdx.x) >> 5;  // 1 warp / row
    const int b    = row >> 12;
    const int pos  = row & (SS - 1);

    const float4* __restrict__ mrow =
        reinterpret_cast<const float4*>(mask + (size_t)row * SS);

    // ---- phase 1: stream 16 KB mask row, build 4 bitmask words per lane ----
    uint4 myw;  // words 4*lane .. 4*lane+3 of this row
#pragma unroll
    for (int i = 0; i < 32; i++) {
        float4 v = mrow[i * 32 + lane];   // coalesced 512B per warp-iter
        unsigned b0 = __ballot_sync(0xFFFFFFFFu, v.x != 0.0f);
        unsigned b1 = __ballot_sync(0xFFFFFFFFu, v.y != 0.0f);
        unsigned b2 = __ballot_sync(0xFFFFFFFFu, v.z != 0.0f);
        unsigned b3 = __ballot_sync(0xFFFFFFFFu, v.w != 0.0f);
        if (lane == i) { myw.x = b0; myw.y = b1; myw.z = b2; myw.w = b3; }
    }

    // Store bitmask (coalesced STG.128; needed by the rare fallback path).
    reinterpret_cast<uint4*>(g_bits + (size_t)row * WPR)[lane] = myw;

    // ---- phase 2: counts + exclusive warp scan ----
    const int n = __popc(myw.x) + __popc(myw.y) + __popc(myw.z) + __popc(myw.w);
    int pfx = n;
#pragma unroll
    for (int off = 1; off < 32; off <<= 1) {
        int v = __shfl_up_sync(0xFFFFFFFFu, pfx, off);
        if (lane >= off) pfx += v;
    }
    const int total = __shfl_sync(0xFFFFFFFFu, pfx, 31);
    pfx -= n;  // exclusive
    if (lane == 0) g_cnt[row] = total;

    // ---- phase 3: scatter indices + accumulate force(psi) for evalA ----
    unsigned short* __restrict__ dst = g_idx + (size_t)row * CAP;
    const float2*   __restrict__ psib = psi + (size_t)b * SS;

    float ax = 0.0f, ay = 0.0f;
    int slot = pfx;
    uint32_t ws[4] = {myw.x, myw.y, myw.z, myw.w};
#pragma unroll
    for (int k = 0; k < 4; k++) {       // word W = 4*lane + k
        uint32_t w = ws[k];
        while (w) {
            int bp = __ffs(w) - 1;
            w &= (w - 1);
            int col = lane * 128 + 4 * bp + k;   // OUR bit convention
            float2 v = psib[col];
            ax += v.x;
            ay += v.y;
            if (slot < CAP) dst[slot] = (unsigned short)col;
            slot++;
        }
    }
    // Fill unused tail with sentinel (disjoint slots; no sync needed).
    for (int i = (total < CAP ? total : CAP) + lane; i < CAP; i += 32)
        dst[i] = (unsigned short)SENT;

    // ---- full-warp force reduce + evalA math ----
#pragma unroll
    for (int off = 16; off > 0; off >>= 1) {
        ax += __shfl_down_sync(0xFFFFFFFFu, ax, off);
        ay += __shfl_down_sync(0xFFFFFFFFu, ay, off);
    }
    if (lane == 0) {
        float2 pi = psib[pos];
        float  r  = sqrtf(pi.x * pi.x + pi.y * pi.y);
        float k1x = ax - pi.x;
        float k1y = ay - pi.y;
        float sx  = fmaf(DT_F, k1x, pi.x);
        float sy  = fmaf(DT_F, k1y, pi.y);
        float sn  = sqrtf(sx * sx + sy * sy);
        float sc  = r / (sn + EPS_F);
        g_sp[b * PS + pos] = make_float2(sx * sc, sy * sc);  // psi_star
        g_k1[row]          = make_float2(k1x, k1y);
        g_r[row]           = r;
        g_ps[b * PS + pos] = pi;                              // state copy
    }
}

// ============================================================================
// Shared-memory gather: unconditional sentinel-padded LDS gathers.
// ============================================================================
__device__ __forceinline__ void smem_force(const float2* __restrict__ sp,
                                           int row, int t,
                                           float& ax, float& ay) {
    ax = 0.0f; ay = 0.0f;
    const int cnt = g_cnt[row];

    if (cnt <= CAP) {
        // t*IPT u16 = 20B offset -> 4B aligned; load as 5 u32.
        const uint32_t* p32 = reinterpret_cast<const uint32_t*>(
            g_idx + (size_t)row * CAP + t * IPT);
        uint32_t a0 = p32[0], a1 = p32[1], a2 = p32[2], a3 = p32[3], a4 = p32[4];
        int id[IPT];
        id[0] = (int)(a0 & 0xFFFFu);  id[1] = (int)(a0 >> 16);
        id[2] = (int)(a1 & 0xFFFFu);  id[3] = (int)(a1 >> 16);
        id[4] = (int)(a2 & 0xFFFFu);  id[5] = (int)(a2 >> 16);
        id[6] = (int)(a3 & 0xFFFFu);  id[7] = (int)(a3 >> 16);
        id[8] = (int)(a4 & 0xFFFFu);  id[9] = (int)(a4 >> 16);
#pragma unroll
        for (int j = 0; j < IPT; j++) {   // 10 unconditional LDS.64
            float2 v = sp[id[j]];
            ax += v.x;
            ay += v.y;
        }
    } else {
        // Correctness fallback (cnt > CAP; ~6-sigma rare). Bitmask scan.
        const uint32_t* wr = g_bits + (size_t)row * WPR + t * WPT;
#pragma unroll
        for (int q = 0; q < WPT; q++) {
            int W = t * WPT + q;
            int i = W >> 2, k = W & 3;
            uint32_t w = wr[q];
            while (w) {
                int bp = __ffs(w) - 1;
                w &= (w - 1);
                float2 v = sp[128 * i + 4 * bp + k];
                ax += v.x;
                ay += v.y;
            }
        }
    }

#pragma unroll
    for (int off = T_PER_ROW / 2; off > 0; off >>= 1) {
        ax += __shfl_down_sync(0xFFFFFFFFu, ax, off, T_PER_ROW);
        ay += __shfl_down_sync(0xFFFFFFFFu, ay, off, T_PER_ROW);
    }
}

// Stage one batch's 32 KB state into smem (float4, 8 iters/thread).
__device__ __forceinline__ void stage(float2* sp, const float2* gsrc, int tid) {
    const float4* src = reinterpret_cast<const float4*>(gsrc);
    float4*       dst = reinterpret_cast<float4*>(sp);
#pragma unroll
    for (int i = 0; i < SS / 2 / 256; i++) dst[tid + i * 256] = src[tid + i * 256];
    if (tid == 0) sp[SS] = make_float2(0.0f, 0.0f);   // sentinel target
}

// ============================================================================
// 2) evalA: k1 = force(p); psi_star = renorm(p + dt*k1). Stages g_ps.
// ============================================================================
__global__ void __launch_bounds__(256)
evalA_kernel() {
    __shared__ __align__(16) float2 sp[SS + 2];
    const int tid = threadIdx.x;
    const int row = blockIdx.x * ROWS_PB + (tid >> 3);
    const int t   = tid & 7;
    const int b   = row >> 12;            // uniform per block (32 | 4096)
    const int pos = row & (SS - 1);

    stage(sp, g_ps + b * PS, tid);
    __syncthreads();

    float ax, ay;
    smem_force(sp, row, t, ax, ay);

    if (t == 0) {
        float2 pi = sp[pos];
        float  r  = sqrtf(pi.x * pi.x + pi.y * pi.y);
        float k1x = ax - pi.x;
        float k1y = ay - pi.y;
        float sx  = fmaf(DT_F, k1x, pi.x);
        float sy  = fmaf(DT_F, k1y, pi.y);
        float sn  = sqrtf(sx * sx + sy * sy);
        float sc  = r / (sn + EPS_F);
        g_sp[b * PS + pos] = make_float2(sx * sc, sy * sc);
        g_k1[row]          = make_float2(k1x, k1y);
        g_r[row]           = r;
    }
}

// ============================================================================
// 3) evalB: k2 = force(psi_star); p = renorm(p + dt/2*(k1+k2)). Stages g_sp.
//    out == nullptr -> write g_ps; else write final result to out.
// ============================================================================
__global__ void __launch_bounds__(256)
evalB_kernel(float2* __restrict__ out) {
    __shared__ __align__(16) float2 sp[SS + 2];
    const int tid = threadIdx.x;
    const int row = blockIdx.x * ROWS_PB + (tid >> 3);
    const int t   = tid & 7;
    const int b   = row >> 12;
    const int pos = row & (SS - 1);

    stage(sp, g_sp + b * PS, tid);
    __syncthreads();

    float ax, ay;
    smem_force(sp, row, t, ax, ay);

    if (t == 0) {
        float2 si = sp[pos];
        float k2x = ax - si.x;
        float k2y = ay - si.y;
        float2 k1 = g_k1[row];
        float2 p  = g_ps[b * PS + pos];
        float  r  = g_r[row];
        float nx  = fmaf(HALF_DT_F, k1.x + k2x, p.x);
        float ny  = fmaf(HALF_DT_F, k1.y + k2y, p.y);
        float nn  = sqrtf(nx * nx + ny * ny);
        float sc  = r / (nn + EPS_F);
        float2 res = make_float2(nx * sc, ny * sc);
        if (out) out[row]          = res;
        else     g_ps[b * PS + pos] = res;
    }
}

// ============================================================================
// Launch: merged front kernel + 5 light evals. All graph-capturable, no atomics.
// ============================================================================
extern "C" void kernel_launch(void* const* d_in, const int* in_sizes, int n_in,
                              void* d_out, int out_size) {
    const float* psi  = (const float*)d_in[0];
    const float* mask = (const float*)d_in[1];
    if (n_in >= 2 && in_sizes[0] > in_sizes[1]) {  // defensive: pick by size
        psi  = (const float*)d_in[1];
        mask = (const float*)d_in[0];
    }

    // Step 1 evalA fused with compression + index build (1 warp per row).
    fused_compress_evalA1<<<NROWS / 8, 256>>>(mask, (const float2*)psi);

    // Remaining 5 force evals.
    evalB_kernel<<<EGRID, 256>>>(nullptr);        // step 1 B
    evalA_kernel<<<EGRID, 256>>>();               // step 2 A
    evalB_kernel<<<EGRID, 256>>>(nullptr);        // step 2 B
    evalA_kernel<<<EGRID, 256>>>();               // step 3 A
    evalB_kernel<<<EGRID, 256>>>((float2*)d_out); // step 3 B -> output

    (void)out_size;
}

// round 13
// speedup vs baseline: 1.3046x; 1.0710x over previous
#include <cuda_runtime.h>
#include <stdint.h>

// Problem constants (fixed by the reference: B=4, S=4096, D=2, 3 RK2 steps)
#define BB    4
#define SS    4096
#define WPR   (SS / 32)            // 128 bitmask words per row
#define NWRDS (BB * SS * WPR)      // 8 MB bitmask
#define NROWS (BB * SS)            // 16384 rows
#define CAP   80                   // padded index capacity (mean 41, sd 6.4; 6 sigma)
#define PS    (SS + 8)             // padded per-batch stride (float2 elems)
#define SENT  SS                   // sentinel index -> zero pad slot (in smem)
#define DT_F      0.1f
#define HALF_DT_F 0.05f
#define EPS_F     1e-8f

// Eval tiling: 8 threads per row, 32 rows per block (256 threads).
#define T_PER_ROW 8
#define IPT       (CAP / T_PER_ROW)   // 10 indices per thread
#define WPT       (WPR / T_PER_ROW)   // 16 bitmask words per thread (fallback)
#define ROWS_PB   32
#define EGRID     (NROWS / ROWS_PB)   // 512 blocks

// Bitmask bit convention (OURS, not lane-major!):
//   word W = 4*i + k  (i = 0..31, k = 0..3), bit b  <->  column 128*i + 4*b + k

// ---- scratch (static device globals; no runtime allocation) ----
__device__ __align__(16) uint32_t       g_bits[NWRDS];
__device__ __align__(16) unsigned short g_idx[NROWS * CAP];   // sentinel-padded CSR
__device__               int            g_cnt[NROWS];         // true nnz per row
__device__ __align__(16) float2         g_ps[BB * PS];        // state p (padded stride)
__device__ __align__(16) float2         g_sp[BB * PS];        // psi_star
__device__ __align__(16) float2         g_k1[NROWS];
__device__               float          g_r[NROWS];

// ============================================================================
// 1) MERGED: compress mask -> bitmask, build CSR indices, AND compute step-1
//    evalA — all in one DRAM-bound pass over the 256 MB mask. 1 warp per row.
// ============================================================================
__global__ void __launch_bounds__(256)
fused_compress_evalA1(const float* __restrict__ mask,
                      const float2* __restrict__ psi) {
    const int lane = threadIdx.x & 31;
    const int row  = (blockIdx.x * blockDim.x + threadIdx.x) >> 5;  // 1 warp / row
    const int b    = row >> 12;
    const int pos  = row & (SS - 1);

    const float4* __restrict__ mrow =
        reinterpret_cast<const float4*>(mask + (size_t)row * SS);

    // ---- phase 1: stream 16 KB mask row, build 4 bitmask words per lane ----
    uint4 myw;
#pragma unroll
    for (int i = 0; i < 32; i++) {
        float4 v = mrow[i * 32 + lane];   // coalesced 512B per warp-iter
        unsigned b0 = __ballot_sync(0xFFFFFFFFu, v.x != 0.0f);
        unsigned b1 = __ballot_sync(0xFFFFFFFFu, v.y != 0.0f);
        unsigned b2 = __ballot_sync(0xFFFFFFFFu, v.z != 0.0f);
        unsigned b3 = __ballot_sync(0xFFFFFFFFu, v.w != 0.0f);
        if (lane == i) { myw.x = b0; myw.y = b1; myw.z = b2; myw.w = b3; }
    }

    reinterpret_cast<uint4*>(g_bits + (size_t)row * WPR)[lane] = myw;

    // ---- phase 2: counts + exclusive warp scan ----
    const int n = __popc(myw.x) + __popc(myw.y) + __popc(myw.z) + __popc(myw.w);
    int pfx = n;
#pragma unroll
    for (int off = 1; off < 32; off <<= 1) {
        int v = __shfl_up_sync(0xFFFFFFFFu, pfx, off);
        if (lane >= off) pfx += v;
    }
    const int total = __shfl_sync(0xFFFFFFFFu, pfx, 31);
    pfx -= n;  // exclusive
    if (lane == 0) g_cnt[row] = total;

    // ---- phase 3: scatter indices + accumulate force(psi) for evalA ----
    unsigned short* __restrict__ dst  = g_idx + (size_t)row * CAP;
    const float2*   __restrict__ psib = psi + (size_t)b * SS;

    float ax = 0.0f, ay = 0.0f;
    int slot = pfx;
    uint32_t ws[4] = {myw.x, myw.y, myw.z, myw.w};
#pragma unroll
    for (int k = 0; k < 4; k++) {       // word W = 4*lane + k
        uint32_t w = ws[k];
        while (w) {
            int bp = __ffs(w) - 1;
            w &= (w - 1);
            int col = lane * 128 + 4 * bp + k;   // OUR bit convention
            float2 v = psib[col];
            ax += v.x;
            ay += v.y;
            if (slot < CAP) dst[slot] = (unsigned short)col;
            slot++;
        }
    }
    for (int i = (total < CAP ? total : CAP) + lane; i < CAP; i += 32)
        dst[i] = (unsigned short)SENT;

#pragma unroll
    for (int off = 16; off > 0; off >>= 1) {
        ax += __shfl_down_sync(0xFFFFFFFFu, ax, off);
        ay += __shfl_down_sync(0xFFFFFFFFu, ay, off);
    }
    if (lane == 0) {
        float2 pi = psib[pos];
        float  r  = sqrtf(pi.x * pi.x + pi.y * pi.y);
        float k1x = ax - pi.x;
        float k1y = ay - pi.y;
        float sx  = fmaf(DT_F, k1x, pi.x);
        float sy  = fmaf(DT_F, k1y, pi.y);
        float sn  = sqrtf(sx * sx + sy * sy);
        float sc  = r / (sn + EPS_F);
        g_sp[b * PS + pos] = make_float2(sx * sc, sy * sc);  // psi_star
        g_k1[row]          = make_float2(k1x, k1y);
        g_r[row]           = r;
        g_ps[b * PS + pos] = pi;                              // state copy
    }
}

// ============================================================================
// cp.async helpers (register-free async smem staging)
// ============================================================================
__device__ __forceinline__ void cpasync16(uint32_t smem_addr, const void* gptr) {
    asm volatile("cp.async.cg.shared.global [%0], [%1], 16;"
                 :: "r"(smem_addr), "l"(gptr) : "memory");
}
__device__ __forceinline__ void cpasync_commit_wait() {
    asm volatile("cp.async.commit_group;" ::: "memory");
    asm volatile("cp.async.wait_group 0;"  ::: "memory");
}

// ============================================================================
// Gather core shared by both eval kernels. The staging is cp.async; the
// per-thread CSR indices / cnt are loaded UNDER the staging latency.
// ============================================================================
struct GatherCtx {
    int id[IPT];
    int cnt;
};

__device__ __forceinline__ void load_indices(GatherCtx& c, int row, int t) {
    c.cnt = g_cnt[row];
    const uint32_t* p32 = reinterpret_cast<const uint32_t*>(
        g_idx + (size_t)row * CAP + t * IPT);   // t*10 u16 = 20B -> 4B aligned
    uint32_t a0 = p32[0], a1 = p32[1], a2 = p32[2], a3 = p32[3], a4 = p32[4];
    c.id[0] = (int)(a0 & 0xFFFFu);  c.id[1] = (int)(a0 >> 16);
    c.id[2] = (int)(a1 & 0xFFFFu);  c.id[3] = (int)(a1 >> 16);
    c.id[4] = (int)(a2 & 0xFFFFu);  c.id[5] = (int)(a2 >> 16);
    c.id[6] = (int)(a3 & 0xFFFFu);  c.id[7] = (int)(a3 >> 16);
    c.id[8] = (int)(a4 & 0xFFFFu);  c.id[9] = (int)(a4 >> 16);
}

__device__ __forceinline__ void gather_reduce(const GatherCtx& c,
                                              const float2* __restrict__ sp,
                                              int row, int t,
                                              float& ax, float& ay) {
    ax = 0.0f; ay = 0.0f;
    if (c.cnt <= CAP) {
#pragma unroll
        for (int j = 0; j < IPT; j++) {   // 10 unconditional LDS.64
            float2 v = sp[c.id[j]];
            ax += v.x;
            ay += v.y;
        }
    } else {
        // Correctness fallback (cnt > CAP; ~6-sigma rare). Bitmask scan.
        const uint32_t* wr = g_bits + (size_t)row * WPR + t * WPT;
#pragma unroll
        for (int q = 0; q < WPT; q++) {
            int W = t * WPT + q;
            int i = W >> 2, k = W & 3;
            uint32_t w = wr[q];
            while (w) {
                int bp = __ffs(w) - 1;
                w &= (w - 1);
                float2 v = sp[128 * i + 4 * bp + k];
                ax += v.x;
                ay += v.y;
            }
        }
    }
#pragma unroll
    for (int off = T_PER_ROW / 2; off > 0; off >>= 1) {
        ax += __shfl_down_sync(0xFFFFFFFFu, ax, off, T_PER_ROW);
        ay += __shfl_down_sync(0xFFFFFFFFu, ay, off, T_PER_ROW);
    }
}

// Issue the 32 KB async stage: 8 x 16B per thread, coalesced.
__device__ __forceinline__ void stage_async(float2* sp, const float2* gsrc, int tid) {
    uint32_t sbase = (uint32_t)__cvta_generic_to_shared(sp);
    const char* g  = reinterpret_cast<const char*>(gsrc);
#pragma unroll
    for (int i = 0; i < SS / 2 / 256; i++) {      // 8 iters
        int e = tid + i * 256;                    // float4 element index
        cpasync16(sbase + e * 16, g + e * 16);
    }
}

// ============================================================================
// 2) evalA: k1 = force(p); psi_star = renorm(p + dt*k1). Stages g_ps.
// ============================================================================
__global__ void __launch_bounds__(256)
evalA_kernel() {
    __shared__ __align__(16) float2 sp[SS + 2];
    const int tid = threadIdx.x;
    const int row = blockIdx.x * ROWS_PB + (tid >> 3);
    const int t   = tid & 7;
    const int b   = row >> 12;            // uniform per block (32 | 4096)
    const int pos = row & (SS - 1);

    stage_async(sp, g_ps + b * PS, tid);  // async, register-free

    GatherCtx c;
    load_indices(c, row, t);              // L2 loads hidden under staging

    cpasync_commit_wait();
    if (tid == 0) sp[SS] = make_float2(0.0f, 0.0f);   // sentinel target
    __syncthreads();

    float ax, ay;
    gather_reduce(c, sp, row, t, ax, ay);

    if (t == 0) {
        float2 pi = sp[pos];
        float  r  = sqrtf(pi.x * pi.x + pi.y * pi.y);
        float k1x = ax - pi.x;
        float k1y = ay - pi.y;
        float sx  = fmaf(DT_F, k1x, pi.x);
        float sy  = fmaf(DT_F, k1y, pi.y);
        float sn  = sqrtf(sx * sx + sy * sy);
        float sc  = r / (sn + EPS_F);
        g_sp[b * PS + pos] = make_float2(sx * sc, sy * sc);
        g_k1[row]          = make_float2(k1x, k1y);
        g_r[row]           = r;
    }
}

// ============================================================================
// 3) evalB: k2 = force(psi_star); p = renorm(p + dt/2*(k1+k2)). Stages g_sp.
//    out == nullptr -> write g_ps; else write final result to out.
// ============================================================================
__global__ void __launch_bounds__(256)
evalB_kernel(float2* __restrict__ out) {
    __shared__ __align__(16) float2 sp[SS + 2];
    const int tid = threadIdx.x;
    const int row = blockIdx.x * ROWS_PB + (tid >> 3);
    const int t   = tid & 7;
    const int b   = row >> 12;
    const int pos = row & (SS - 1);

    stage_async(sp, g_sp + b * PS, tid);  // async, register-free

    GatherCtx c;
    load_indices(c, row, t);              // hidden under staging

    // t==0 auxiliary operands, also hidden under staging latency.
    float2 k1 = make_float2(0.f, 0.f), p = make_float2(0.f, 0.f);
    float  r  = 0.f;
    if (t == 0) {
        k1 = g_k1[row];
        p  = g_ps[b * PS + pos];
        r  = g_r[row];
    }

    cpasync_commit_wait();
    if (tid == 0) sp[SS] = make_float2(0.0f, 0.0f);
    __syncthreads();

    float ax, ay;
    gather_reduce(c, sp, row, t, ax, ay);

    if (t == 0) {
        float2 si = sp[pos];
        float k2x = ax - si.x;
        float k2y = ay - si.y;
        float nx  = fmaf(HALF_DT_F, k1.x + k2x, p.x);
        float ny  = fmaf(HALF_DT_F, k1.y + k2y, p.y);
        float nn  = sqrtf(nx * nx + ny * ny);
        float sc  = r / (nn + EPS_F);
        float2 res = make_float2(nx * sc, ny * sc);
        if (out) out[row]           = res;
        else     g_ps[b * PS + pos] = res;
    }
}

// ============================================================================
// Launch: merged front kernel + 5 light evals. All graph-capturable, no atomics.
// ============================================================================
extern "C" void kernel_launch(void* const* d_in, const int* in_sizes, int n_in,
                              void* d_out, int out_size) {
    const float* psi  = (const float*)d_in[0];
    const float* mask = (const float*)d_in[1];
    if (n_in >= 2 && in_sizes[0] > in_sizes[1]) {  // defensive: pick by size
        psi  = (const float*)d_in[1];
        mask = (const float*)d_in[0];
    }

    // Step 1 evalA fused with compression + index build (1 warp per row).
    fused_compress_evalA1<<<NROWS / 8, 256>>>(mask, (const float2*)psi);

    // Remaining 5 force evals.
    evalB_kernel<<<EGRID, 256>>>(nullptr);        // step 1 B
    evalA_kernel<<<EGRID, 256>>>();               // step 2 A
    evalB_kernel<<<EGRID, 256>>>(nullptr);        // step 2 B
    evalA_kernel<<<EGRID, 256>>>();               // step 3 A
    evalB_kernel<<<EGRID, 256>>>((float2*)d_out); // step 3 B -> output

    (void)out_size;
}